// round 1
// baseline (speedup 1.0000x reference)
#include <cuda_runtime.h>

// HierarchicalRouter: two-level MoE router.
//   x               [16384, 2048] f32
//   group_gate_w    [8, 2048]     f32
//   expert_gate_w   [64, 2048]    f32
// out = concat(valid_mask[16384,64] as f32 0/1, normalized_weights[16384,64])
//
// Strategy: fused GEMM (M=16384, N=72, K=2048) using packed fp32x2 FFMA
// (fma.rn.f32x2, 2x scalar FFMA throughput on sm_103a), tiled
// BM=128 x N=72 per block, BK=16 double-buffered smem, thread tile
// 4 tokens x 9 experts. Epilogue: per-token softmaxes/masks/normalize.

#define N_TOKENS 16384
#define DIM      2048
#define BM       128
#define BK       16
#define NITER    (DIM / BK)
#define THREADS  256
#define WSTRIDE  73   // padded expert stride in smem (conflict-free stores)

__device__ __forceinline__ void ffma2(unsigned long long& acc,
                                      unsigned long long a,
                                      unsigned long long b) {
    asm("fma.rn.f32x2 %0, %1, %2, %0;" : "+l"(acc) : "l"(a), "l"(b));
}

__device__ __forceinline__ unsigned long long splat2(float w) {
    unsigned long long r;
    asm("mov.b64 %0, {%1, %1};" : "=l"(r) : "f"(w));
    return r;
}

struct SmemTiles {
    float xs[2][BK][BM];       // transposed x tile: [buf][k][token]
    float ws[2][BK][WSTRIDE];  // w tile: [buf][k][expert(0..71)]
};

__global__ __launch_bounds__(THREADS, 1)
void router_kernel(const float* __restrict__ x,
                   const float* __restrict__ ggw,
                   const float* __restrict__ egw,
                   float* __restrict__ out)
{
    __shared__ union {
        SmemTiles t;
        float logits[BM * WSTRIDE];  // reused after mainloop
    } sm;

    const int tid  = threadIdx.x;
    const int tg   = tid & 31;        // token group: tokens 4*tg .. 4*tg+3
    const int egp  = tid >> 5;        // expert group 0..7 (one per warp)
    const int e0   = egp * 9;         // experts e0..e0+8
    const int tok0 = blockIdx.x * BM;

    // ---- gmem loader mapping ----
    // x: thread (ltok, lhalf) loads float4 at k-quads {lhalf, 2+lhalf}
    //    -> adjacent lanes read adjacent 16B (full 32B sectors).
    const int ltok  = tid >> 1;
    const int lhalf = tid & 1;
    const float* xrow = x + (size_t)(tok0 + ltok) * DIM;

    // w: i in [0,288): e = i>>2, q = i&3; thread does i=tid (+256 if tid<32)
    const int we0 = tid >> 2;           // 0..63
    const int wq0 = tid & 3;
    const float* wrow0 = (we0 < 8) ? (ggw + (size_t)we0 * DIM)
                                   : (egw + (size_t)(we0 - 8) * DIM);
    const int we1 = (tid + 256) >> 2;   // 64..71 (tid<32 only)
    const int wq1 = (tid + 256) & 3;
    const float* wrow1 = egw + (size_t)(we1 - 8) * DIM;

    unsigned long long acc[2][9];
#pragma unroll
    for (int p = 0; p < 2; p++)
#pragma unroll
        for (int j = 0; j < 9; j++) acc[p][j] = 0ull;

    float4 xa, xb, wa, wb;

    auto ldg_tile = [&](int it) {
        const int k0 = it * BK;
        xa = *reinterpret_cast<const float4*>(xrow + k0 + lhalf * 4);
        xb = *reinterpret_cast<const float4*>(xrow + k0 + (2 + lhalf) * 4);
        wa = *reinterpret_cast<const float4*>(wrow0 + k0 + wq0 * 4);
        if (tid < 32)
            wb = *reinterpret_cast<const float4*>(wrow1 + k0 + wq1 * 4);
    };

    auto sts_tile = [&](int b) {
        // x transpose: 2-way store conflict max (ltok shared by 2 lanes)
        sm.t.xs[b][lhalf * 4 + 0][ltok] = xa.x;
        sm.t.xs[b][lhalf * 4 + 1][ltok] = xa.y;
        sm.t.xs[b][lhalf * 4 + 2][ltok] = xa.z;
        sm.t.xs[b][lhalf * 4 + 3][ltok] = xa.w;
        sm.t.xs[b][(2 + lhalf) * 4 + 0][ltok] = xb.x;
        sm.t.xs[b][(2 + lhalf) * 4 + 1][ltok] = xb.y;
        sm.t.xs[b][(2 + lhalf) * 4 + 2][ltok] = xb.z;
        sm.t.xs[b][(2 + lhalf) * 4 + 3][ltok] = xb.w;
        sm.t.ws[b][wq0 * 4 + 0][we0] = wa.x;
        sm.t.ws[b][wq0 * 4 + 1][we0] = wa.y;
        sm.t.ws[b][wq0 * 4 + 2][we0] = wa.z;
        sm.t.ws[b][wq0 * 4 + 3][we0] = wa.w;
        if (tid < 32) {
            sm.t.ws[b][wq1 * 4 + 0][we1] = wb.x;
            sm.t.ws[b][wq1 * 4 + 1][we1] = wb.y;
            sm.t.ws[b][wq1 * 4 + 2][we1] = wb.z;
            sm.t.ws[b][wq1 * 4 + 3][we1] = wb.w;
        }
    };

    auto compute = [&](int b) {
#pragma unroll
        for (int k = 0; k < BK; k++) {
            // two packed token-pairs, directly from smem (16B aligned)
            ulonglong2 xp = *reinterpret_cast<const ulonglong2*>(
                &sm.t.xs[b][k][tg * 4]);
#pragma unroll
            for (int j = 0; j < 9; j++) {
                unsigned long long wp = splat2(sm.t.ws[b][k][e0 + j]);
                ffma2(acc[0][j], xp.x, wp);
                ffma2(acc[1][j], xp.y, wp);
            }
        }
    };

    // ---- mainloop: double-buffered ----
    ldg_tile(0);
    sts_tile(0);
    __syncthreads();
    int cur = 0;
    for (int it = 0; it < NITER; ++it) {
        if (it + 1 < NITER) ldg_tile(it + 1);
        compute(cur);
        if (it + 1 < NITER) sts_tile(cur ^ 1);
        __syncthreads();
        cur ^= 1;
    }

    // ---- stage logits to smem: [token][expert], stride WSTRIDE ----
#pragma unroll
    for (int j = 0; j < 9; j++) {
        float2 p0 = *reinterpret_cast<float2*>(&acc[0][j]);
        float2 p1 = *reinterpret_cast<float2*>(&acc[1][j]);
        const int e = e0 + j;
        sm.logits[(tg * 4 + 0) * WSTRIDE + e] = p0.x;
        sm.logits[(tg * 4 + 1) * WSTRIDE + e] = p0.y;
        sm.logits[(tg * 4 + 2) * WSTRIDE + e] = p1.x;
        sm.logits[(tg * 4 + 3) * WSTRIDE + e] = p1.y;
    }
    __syncthreads();

    // ---- epilogue: one thread per token ----
    if (tid < BM) {
        float* L = &sm.logits[tid * WSTRIDE];  // [0..7] group, [8..71] expert

        // group softmax
        float gl[8];
#pragma unroll
        for (int g = 0; g < 8; g++) gl[g] = L[g];
        float gmax = gl[0];
#pragma unroll
        for (int g = 1; g < 8; g++) gmax = fmaxf(gmax, gl[g]);
        float ge[8], gsum = 0.0f;
#pragma unroll
        for (int g = 0; g < 8; g++) { ge[g] = expf(gl[g] - gmax); gsum += ge[g]; }
        float gp[8];
#pragma unroll
        for (int g = 0; g < 8; g++) gp[g] = ge[g] / gsum;

        unsigned long long vmask = 0ull;
        float swsum = 0.0f;
#pragma unroll
        for (int g = 0; g < 8; g++) {
            const bool gm = (gp[g] >= 0.125f);
            float el[8];
#pragma unroll
            for (int e = 0; e < 8; e++) el[e] = L[8 + g * 8 + e];
            float emax = el[0];
#pragma unroll
            for (int e = 1; e < 8; e++) emax = fmaxf(emax, el[e]);
            float ee[8], esum = 0.0f;
#pragma unroll
            for (int e = 0; e < 8; e++) { ee[e] = expf(el[e] - emax); esum += ee[e]; }
#pragma unroll
            for (int e = 0; e < 8; e++) {
                const float ep = ee[e] / esum;
                const bool val = gm && (ep >= 0.125f);
                const float sw = val ? gp[g] * ep : 0.0f;
                swsum += sw;
                L[8 + g * 8 + e] = sw;  // overwrite logit with selected weight
                if (val) vmask |= (1ull << (g * 8 + e));
            }
        }
        swsum = fmaxf(swsum, 1e-9f);
        const float inv = 1.0f / swsum;

        const int gt = tok0 + tid;
        float* om = out + (size_t)gt * 64;
        float* ow = out + (size_t)N_TOKENS * 64 + (size_t)gt * 64;
#pragma unroll
        for (int i = 0; i < 64; i += 4) {
            float4 m4, w4;
            m4.x = ((vmask >> (i + 0)) & 1ull) ? 1.0f : 0.0f;
            m4.y = ((vmask >> (i + 1)) & 1ull) ? 1.0f : 0.0f;
            m4.z = ((vmask >> (i + 2)) & 1ull) ? 1.0f : 0.0f;
            m4.w = ((vmask >> (i + 3)) & 1ull) ? 1.0f : 0.0f;
            w4.x = L[8 + i + 0] * inv;
            w4.y = L[8 + i + 1] * inv;
            w4.z = L[8 + i + 2] * inv;
            w4.w = L[8 + i + 3] * inv;
            *reinterpret_cast<float4*>(om + i) = m4;
            *reinterpret_cast<float4*>(ow + i) = w4;
        }
    }
}

extern "C" void kernel_launch(void* const* d_in, const int* in_sizes, int n_in,
                              void* d_out, int out_size) {
    const float* x   = (const float*)d_in[0];
    const float* ggw = (const float*)d_in[1];
    const float* egw = (const float*)d_in[2];
    float* out = (float*)d_out;

    const int tokens = in_sizes[0] / DIM;   // 16384
    const int grid = tokens / BM;           // 128
    router_kernel<<<grid, THREADS>>>(x, ggw, egw, out);
}